// round 5
// baseline (speedup 1.0000x reference)
#include <cuda_runtime.h>
#include <cstdint>

// ChessboardLayer: (B,H,W,C)=(32,256,256,32) fp32 space-to-depth into 8x8 cells.
// Pure 4KiB-block transpose:
//   in  chunk id q = br*256 + i*8 + c
//   out chunk id   = br*256 + c*32 + i
//
// R4: persistent grid-stride (single wave: 152 SMs x 8 CTAs = 1216 CTAs).
// Each iteration = R2's winning layout: 4 consecutive input chunks
// (16 KiB contiguous read, MLP=4 batched loads) -> 4 x 4 KiB writes.
// Next iteration's loads are independent of current stores -> scoreboard
// overlaps across iterations; no wave-transition exposure.

__global__ void __launch_bounds__(256, 8)
chessboard_kernel(const float4* __restrict__ in, float4* __restrict__ out,
                  unsigned ngroups) {
    unsigned t = threadIdx.x;
    for (unsigned g = blockIdx.x; g < ngroups; g += gridDim.x) {
        unsigned base = g * 4u;

        float4 v0 = __ldcs(&in[(size_t)(base + 0u) * 256u + t]);
        float4 v1 = __ldcs(&in[(size_t)(base + 1u) * 256u + t]);
        float4 v2 = __ldcs(&in[(size_t)(base + 2u) * 256u + t]);
        float4 v3 = __ldcs(&in[(size_t)(base + 3u) * 256u + t]);

        #pragma unroll
        for (int k = 0; k < 4; k++) {
            unsigned q  = base + (unsigned)k;
            unsigned oc = (q >> 8) * 256u + (q & 7u) * 32u + ((q >> 3) & 31u);
            float4 v = (k == 0) ? v0 : (k == 1) ? v1 : (k == 2) ? v2 : v3;
            __stcs(&out[(size_t)oc * 256u + t], v);
        }
    }
}

extern "C" void kernel_launch(void* const* d_in, const int* in_sizes, int n_in,
                              void* d_out, int out_size) {
    const float4* in  = (const float4*)d_in[0];
    float4*       out = (float4*)d_out;
    // 65536 chunks / 4 per group = 16384 groups; one wave of CTAs.
    chessboard_kernel<<<1216, 256>>>(in, out, 16384u);
}

// round 6
// speedup vs baseline: 1.1191x; 1.1191x over previous
#include <cuda_runtime.h>
#include <cstdint>

// ChessboardLayer: (B,H,W,C)=(32,256,256,32) fp32 space-to-depth into 8x8 cells.
// Pure 4KiB-block transpose:
//   in  chunk id q = br*256 + i*8 + c
//   out chunk id o = br*256 + c*32 + i
//
// R5: invert R2 — each CTA owns 4 CONSECUTIVE OUTPUT chunks:
//   write: 16 KiB fully contiguous
//   read : 4 x 4 KiB streams at 32 KiB stride (MLP=4 batched)
// Isolates whether HBM write-side locality (row/bank churn, bus turnaround)
// is the residual binder vs read-side.

__global__ void __launch_bounds__(256, 8)
chessboard_kernel(const float4* __restrict__ in, float4* __restrict__ out) {
    unsigned obase = blockIdx.x * 4u;    // first output chunk id
    unsigned t     = threadIdx.x;

    // o = obase + k. Aligned 4-group: br, c shared; i = i0 + k.
    unsigned i0 = obase & 31u;
    unsigned c  = (obase >> 5) & 7u;
    unsigned br = obase >> 8;

    // input chunk q(k) = br*256 + (i0+k)*8 + c  -> stride 8 chunks (2048 f4)
    const float4* ib = in + (size_t)(br * 256u + i0 * 8u + c) * 256u + t;

    float4 v0 = __ldcs(ib + 0u * 2048u);
    float4 v1 = __ldcs(ib + 1u * 2048u);
    float4 v2 = __ldcs(ib + 2u * 2048u);
    float4 v3 = __ldcs(ib + 3u * 2048u);

    float4* ob = out + (size_t)obase * 256u + t;
    __stcs(ob + 0u * 256u, v0);
    __stcs(ob + 1u * 256u, v1);
    __stcs(ob + 2u * 256u, v2);
    __stcs(ob + 3u * 256u, v3);
}

extern "C" void kernel_launch(void* const* d_in, const int* in_sizes, int n_in,
                              void* d_out, int out_size) {
    const float4* in  = (const float4*)d_in[0];
    float4*       out = (float4*)d_out;
    // 65536 output chunks / 4 per CTA = 16384 CTAs
    chessboard_kernel<<<16384, 256>>>(in, out);
}

// round 7
// speedup vs baseline: 1.1204x; 1.0012x over previous
#include <cuda_runtime.h>
#include <cstdint>

// ChessboardLayer: (B,H,W,C)=(32,256,256,32) fp32 space-to-depth into 8x8 cells.
// Pure 4KiB-block transpose:
//   in  chunk id q = br*256 + i*8 + c
//   out chunk id o = br*256 + c*32 + i
//
// R6: R5 orientation (contiguous writes) with doubled batch depth:
//   each CTA owns 8 consecutive OUTPUT chunks -> 32 KiB contiguous write,
//   8 front-batched reads (MLP_p1=8), each 4 KiB contiguous, 32 KiB stride.
// Deeper outstanding-read window lets the DRAM scheduler amortize
// read<->write bus turnarounds.

__global__ void __launch_bounds__(256)
chessboard_kernel(const float4* __restrict__ in, float4* __restrict__ out) {
    unsigned obase = blockIdx.x * 8u;    // first output chunk id
    unsigned t     = threadIdx.x;

    // o = obase + k, k=0..7. obase multiple of 8 => i0 = obase&31 in {0,8,16,24},
    // i0+7 <= 31, so all 8 share (br, c); i = i0 + k.
    unsigned i0 = obase & 31u;
    unsigned c  = (obase >> 5) & 7u;
    unsigned br = obase >> 8;

    // input chunk q(k) = br*256 + (i0+k)*8 + c  -> stride 8 chunks = 2048 f4
    const float4* ib = in + (size_t)(br * 256u + i0 * 8u + c) * 256u + t;

    float4 v0 = __ldcs(ib + 0u * 2048u);
    float4 v1 = __ldcs(ib + 1u * 2048u);
    float4 v2 = __ldcs(ib + 2u * 2048u);
    float4 v3 = __ldcs(ib + 3u * 2048u);
    float4 v4 = __ldcs(ib + 4u * 2048u);
    float4 v5 = __ldcs(ib + 5u * 2048u);
    float4 v6 = __ldcs(ib + 6u * 2048u);
    float4 v7 = __ldcs(ib + 7u * 2048u);

    float4* ob = out + (size_t)obase * 256u + t;
    __stcs(ob + 0u * 256u, v0);
    __stcs(ob + 1u * 256u, v1);
    __stcs(ob + 2u * 256u, v2);
    __stcs(ob + 3u * 256u, v3);
    __stcs(ob + 4u * 256u, v4);
    __stcs(ob + 5u * 256u, v5);
    __stcs(ob + 6u * 256u, v6);
    __stcs(ob + 7u * 256u, v7);
}

extern "C" void kernel_launch(void* const* d_in, const int* in_sizes, int n_in,
                              void* d_out, int out_size) {
    const float4* in  = (const float4*)d_in[0];
    float4*       out = (float4*)d_out;
    // 65536 output chunks / 8 per CTA = 8192 CTAs
    chessboard_kernel<<<8192, 256>>>(in, out);
}